// round 4
// baseline (speedup 1.0000x reference)
#include <cuda_runtime.h>
#include <cstdint>

#define N_MAX 4096
#define W_MAX 128              // words per row (N_MAX/32)
#define FULLMASK 0xFFFFFFFFu

// Static scratch (allocations forbidden).
__device__ float4   g_pos4[N_MAX];
__device__ int      g_count[N_MAX];        // rows >= n never written -> stay 0
__device__ int      g_offset[N_MAX];
__device__ int      g_total;
__device__ unsigned g_mask[N_MAX * W_MAX]; // 2 MB ballot bitmap

// ---------------------------------------------------------------------------
// Pack pos (N,3)+batch into float4; pad [n, n_pad) with sentinel batch=-2.
__global__ void pack_kernel(const float* __restrict__ pos,
                            const int* __restrict__ batch, int n, int n_pad) {
    int i = blockIdx.x * blockDim.x + threadIdx.x;
    if (i < n) {
        float4 p;
        p.x = pos[3 * i + 0];
        p.y = pos[3 * i + 1];
        p.z = pos[3 * i + 2];
        p.w = __int_as_float(batch[i]);
        g_pos4[i] = p;
    } else if (i < n_pad) {
        g_pos4[i] = make_float4(1e9f, 1e9f, 1e9f, __int_as_float(-2));
    }
}

// ---------------------------------------------------------------------------
// Pass A: one warp per TWO rows (i0, i0+1). Each pj load is shared by both
// rows. Diagonal (j==i) is cleared post-ballot instead of per-pair tests.
__global__ void mask_kernel(int n, int nw) {
    int wid  = (blockIdx.x * blockDim.x + threadIdx.x) >> 5;
    int lane = threadIdx.x & 31;
    int i0 = wid * 2, i1 = i0 + 1;
    if (i0 >= n) return;
    bool has1 = (i1 < n);
    float4 p0 = g_pos4[i0];
    float4 p1 = g_pos4[has1 ? i1 : i0];
    int b0bits = __float_as_int(p0.w);
    int b1bits = __float_as_int(p1.w);
    unsigned* mrow0 = g_mask + (size_t)i0 * nw;
    unsigned* mrow1 = g_mask + (size_t)i1 * nw;
    int dw0 = i0 >> 5, db0 = i0 & 31;
    int dw1 = i1 >> 5, db1 = i1 & 31;
    int c0 = 0, c1 = 0;
#pragma unroll 4
    for (int w = 0; w < nw; w++) {
        int j = w * 32 + lane;
        float4 pj = g_pos4[j];
        int jb = __float_as_int(pj.w);

        float dx0 = __fadd_rn(p0.x, -pj.x);
        float dy0 = __fadd_rn(p0.y, -pj.y);
        float dz0 = __fadd_rn(p0.z, -pj.z);
        float d20 = __fadd_rn(__fadd_rn(__fmul_rn(dx0, dx0), __fmul_rn(dy0, dy0)),
                              __fmul_rn(dz0, dz0));
        float dx1 = __fadd_rn(p1.x, -pj.x);
        float dy1 = __fadd_rn(p1.y, -pj.y);
        float dz1 = __fadd_rn(p1.z, -pj.z);
        float d21 = __fadd_rn(__fadd_rn(__fmul_rn(dx1, dx1), __fmul_rn(dy1, dy1)),
                              __fmul_rn(dz1, dz1));

        bool q0 = (b0bits == jb) & (d20 < 25.0f);
        bool q1 = (b1bits == jb) & (d21 < 25.0f);
        if (q0) q0 = (__fsqrt_rn(d20) < 5.0f);   // exact borderline semantics
        if (q1) q1 = (__fsqrt_rn(d21) < 5.0f);
        unsigned m0 = __ballot_sync(FULLMASK, q0);
        unsigned m1 = __ballot_sync(FULLMASK, q1);
        if (w == dw0) m0 &= ~(1u << db0);        // drop self-pair
        if (w == dw1) m1 &= ~(1u << db1);
        c0 += __popc(m0);
        c1 += __popc(m1);
        if (lane == 0) mrow0[w] = m0;
        if (lane == 1 && has1) mrow1[w] = m1;
    }
    if (lane == 0) g_count[i0] = c0;
    if (lane == 1 && has1) g_count[i1] = c1;
}

// ---------------------------------------------------------------------------
// Exclusive scan of 4096 counts (shfl, 2 barriers). Publishes g_total.
__device__ __forceinline__ int warp_inc_scan(int v, int lane) {
#pragma unroll
    for (int off = 1; off < 32; off <<= 1) {
        int u = __shfl_up_sync(FULLMASK, v, off);
        if (lane >= off) v += u;
    }
    return v;
}

__global__ void scan_kernel() {
    __shared__ int wsum[32];
    int t = threadIdx.x;            // 1024 threads x 4 counts = 4096
    int lane = t & 31, w = t >> 5;
    int4 c = reinterpret_cast<int4*>(g_count)[t];
    int tot = c.x + c.y + c.z + c.w;
    int inc = warp_inc_scan(tot, lane);
    if (lane == 31) wsum[w] = inc;
    __syncthreads();
    if (w == 0) {
        int x = warp_inc_scan(wsum[lane], lane);
        wsum[lane] = x;
    }
    __syncthreads();
    int base = (w ? wsum[w - 1] : 0) + (inc - tot);
    int4 o;
    o.x = base;
    o.y = base + c.x;
    o.z = o.y + c.y;
    o.w = o.z + c.z;
    reinterpret_cast<int4*>(g_offset)[t] = o;
    if (t == 0) g_total = wsum[31];
}

// ---------------------------------------------------------------------------
// Tail init: runs AFTER scan. Writes only slots >= g_total (fill covers the
// prefix). Regions: [0,mp)=-1, [mp,2mp)=-1, [2mp,3mp)=0, [3mp,6mp)=0 (vec).
__global__ void init_tail_kernel(float* __restrict__ out, int mp) {
    long long e = (long long)(blockIdx.x * (long long)blockDim.x + threadIdx.x) * 4;
    long long total6 = 6LL * mp;
    if (e >= total6) return;
    int tt = g_total;
    if (tt > mp) tt = mp;
    long long m2 = 2LL * mp, m3 = 3LL * mp;
    if (e < m3) {
        // scalar-slot regions; a float4 never crosses a region boundary (mp%4==0)
        long long r = (e < (long long)mp) ? 0 : (e < m2 ? 1 : 2);
        int slot0 = (int)(e - r * mp);
        float v = (r < 2) ? -1.0f : 0.0f;
        if (slot0 >= tt) {
            *reinterpret_cast<float4*>(out + e) = make_float4(v, v, v, v);
        } else if (slot0 + 3 >= tt) {
#pragma unroll
            for (int k = 0; k < 4; k++)
                if (slot0 + k >= tt) out[e + k] = v;
        }
    } else {
        long long ve = e - m3;              // element within vec region
        int s0 = (int)(ve / 3);
        int s3 = (int)((ve + 3) / 3);
        if (s0 >= tt) {
            *reinterpret_cast<float4*>(out + e) = make_float4(0.f, 0.f, 0.f, 0.f);
        } else if (s3 >= tt) {
#pragma unroll
            for (int k = 0; k < 4; k++)
                if ((int)((ve + k) / 3) >= tt) out[e + k] = 0.0f;
        }
    }
}

// ---------------------------------------------------------------------------
// Pass B: expand persisted masks (diagonal pre-cleared). One warp per row.
__global__ void fill_kernel(float* __restrict__ out, int n, int mp, int nw) {
    int row = (blockIdx.x * blockDim.x + threadIdx.x) >> 5;
    int lane = threadIdx.x & 31;
    if (row >= n) return;
    float4 pi = g_pos4[row];
    const unsigned* mrow = g_mask + (size_t)row * nw;
    int base = g_offset[row];
    float fi = (float)row;
    for (int w0 = 0; w0 < nw; w0 += 32) {
        unsigned m = mrow[w0 + lane];
        int pc = __popc(m);
        int inc = warp_inc_scan(pc, lane);
        int tot = __shfl_sync(FULLMASK, inc, 31);
        int slot = base + inc - pc;
        while (m) {
            int b = __ffs(m) - 1;
            m &= m - 1;
            int j = (w0 + lane) * 32 + b;
            float4 pj = g_pos4[j];
            float dx = __fadd_rn(pi.x, -pj.x);
            float dy = __fadd_rn(pi.y, -pj.y);
            float dz = __fadd_rn(pi.z, -pj.z);
            float d2 = __fadd_rn(__fadd_rn(__fmul_rn(dx, dx), __fmul_rn(dy, dy)),
                                 __fmul_rn(dz, dz));
            if (slot < mp) {
                out[slot]          = fi;
                out[mp + slot]     = (float)j;
                out[2 * mp + slot] = __fsqrt_rn(d2);
                float* v = out + 3 * mp + 3 * slot;
                v[0] = dx; v[1] = dy; v[2] = dz;
            }
            slot++;
        }
        base += tot;
    }
}

// ---------------------------------------------------------------------------
extern "C" void kernel_launch(void* const* d_in, const int* in_sizes, int n_in,
                              void* d_out, int out_size) {
    const float* pos   = (const float*)d_in[0];
    const int*   batch = (const int*)d_in[1];
    float* out = (float*)d_out;

    int n = in_sizes[1];
    if (n > N_MAX) n = N_MAX;
    int n_pad = (n + 31) & ~31;
    int nw = n_pad / 32;
    int mp = out_size / 6;

    pack_kernel<<<(n_pad + 255) / 256, 256>>>(pos, batch, n, n_pad);

    int mwarps = (n + 1) / 2;
    mask_kernel<<<(mwarps * 32 + 255) / 256, 256>>>(n, nw);
    scan_kernel<<<1, 1024>>>();

    long long vec4 = (6LL * mp + 3) / 4;
    init_tail_kernel<<<(int)((vec4 + 255) / 256), 256>>>(out, mp);

    fill_kernel<<<(n * 32 + 255) / 256, 256>>>(out, n, mp, nw);
}

// round 5
// speedup vs baseline: 2.1156x; 2.1156x over previous
#include <cuda_runtime.h>
#include <cstdint>

#define N_MAX 4096
#define W_MAX 128              // words per row (N_MAX/32)
#define FULLMASK 0xFFFFFFFFu

// Static scratch (allocations forbidden; zero-init at load, rows>=n never dirtied).
__device__ float4   g_pos4[N_MAX];
__device__ int      g_count[N_MAX];
__device__ int      g_offset[N_MAX];
__device__ unsigned g_mask[N_MAX * W_MAX];   // 2 MB ballot bitmap, row-major words

// ---------------------------------------------------------------------------
// Pack pos (N,3)+batch into float4; pad [n, n_pad) with per-row-distinct
// sentinel batch so padded rows never match anything (including each other).
__global__ void pack_kernel(const float* __restrict__ pos,
                            const int* __restrict__ batch, int n, int n_pad) {
    int i = blockIdx.x * blockDim.x + threadIdx.x;
    if (i < n) {
        float4 p;
        p.x = pos[3 * i + 0];
        p.y = pos[3 * i + 1];
        p.z = pos[3 * i + 2];
        p.w = __int_as_float(batch[i]);
        g_pos4[i] = p;
    } else if (i < n_pad) {
        g_pos4[i] = make_float4(1e9f, 1e9f, 1e9f, __int_as_float(-2 - i));
    }
}

// Full output init (simple, proven): edge_index = -1, weight/vec = 0.
__global__ void init_kernel(float* __restrict__ out, int mp) {
    long long idx = (long long)(blockIdx.x * (long long)blockDim.x + threadIdx.x) * 4;
    if (idx < 6LL * mp) {
        float v = (idx < 2LL * mp) ? -1.0f : 0.0f;
        *reinterpret_cast<float4*>(out + idx) = make_float4(v, v, v, v);
    }
}

// ---------------------------------------------------------------------------
// Pass A: symmetric 32x32 tile evaluation. One warp per tile (I,J), J>=I.
// Lane l owns row i=I*32+l. J-tile positions broadcast from smem; step k
// evaluates column j=J*32+k. Local word = row block; ballot = transposed block.
__global__ void mask_block_kernel(int nw) {
    int I = blockIdx.y;
    int wslot = threadIdx.x >> 5;
    int J = blockIdx.x * 8 + wslot;
    int lane = threadIdx.x & 31;
    if (J >= nw || J < I) return;

    __shared__ float4 sh[8][32];
    float4 pi = g_pos4[I * 32 + lane];
    sh[wslot][lane] = g_pos4[J * 32 + lane];
    __syncwarp();
    int ib = __float_as_int(pi.w);

    unsigned myword = 0;
    if (I == J) {
#pragma unroll 8
        for (int k = 0; k < 32; k++) {
            float4 q = sh[wslot][k];
            float dx = __fadd_rn(pi.x, -q.x);
            float dy = __fadd_rn(pi.y, -q.y);
            float dz = __fadd_rn(pi.z, -q.z);
            float d2 = __fadd_rn(__fadd_rn(__fmul_rn(dx, dx), __fmul_rn(dy, dy)),
                                 __fmul_rn(dz, dz));
            bool p = (ib == __float_as_int(q.w)) & (d2 < 25.0f) & (k != lane);
            if (p) p = (__fsqrt_rn(d2) < 5.0f);
            myword |= ((unsigned)p) << k;
        }
        g_mask[(size_t)(I * 32 + lane) * nw + J] = myword;
    } else {
        unsigned tword = 0;
#pragma unroll 8
        for (int k = 0; k < 32; k++) {
            float4 q = sh[wslot][k];
            float dx = __fadd_rn(pi.x, -q.x);
            float dy = __fadd_rn(pi.y, -q.y);
            float dz = __fadd_rn(pi.z, -q.z);
            float d2 = __fadd_rn(__fadd_rn(__fmul_rn(dx, dx), __fmul_rn(dy, dy)),
                                 __fmul_rn(dz, dz));
            bool p = (ib == __float_as_int(q.w)) & (d2 < 25.0f);
            if (p) p = (__fsqrt_rn(d2) < 5.0f);
            unsigned bal = __ballot_sync(FULLMASK, p);   // bit m = pred(I*32+m, J*32+k)
            myword |= ((unsigned)p) << k;
            if (lane == k) tword = bal;                  // symmetric: row J*32+k, word I
        }
        g_mask[(size_t)(I * 32 + lane) * nw + J] = myword;
        g_mask[(size_t)(J * 32 + lane) * nw + I] = tword;
    }
}

// ---------------------------------------------------------------------------
// Per-row popcount: one warp per row, 4 words/lane via uint4, warp reduce.
__global__ void count_kernel(int n_pad, int nw) {
    int row  = (blockIdx.x * blockDim.x + threadIdx.x) >> 5;
    int lane = threadIdx.x & 31;
    if (row >= n_pad) return;
    const unsigned* mrow = g_mask + (size_t)row * nw;
    int s = 0;
    for (int w = lane * 4; w < nw; w += 128) {
        uint4 m = *reinterpret_cast<const uint4*>(mrow + w);
        s += __popc(m.x) + __popc(m.y) + __popc(m.z) + __popc(m.w);
    }
#pragma unroll
    for (int off = 16; off; off >>= 1) s += __shfl_down_sync(FULLMASK, s, off);
    if (lane == 0) g_count[row] = s;
}

// ---------------------------------------------------------------------------
// Exclusive scan of 4096 counts (shfl, 2 barriers).
__device__ __forceinline__ int warp_inc_scan(int v, int lane) {
#pragma unroll
    for (int off = 1; off < 32; off <<= 1) {
        int u = __shfl_up_sync(FULLMASK, v, off);
        if (lane >= off) v += u;
    }
    return v;
}

__global__ void scan_kernel() {
    __shared__ int wsum[32];
    int t = threadIdx.x;            // 1024 threads x 4 counts = 4096
    int lane = t & 31, w = t >> 5;
    int4 c = reinterpret_cast<int4*>(g_count)[t];
    int tot = c.x + c.y + c.z + c.w;
    int inc = warp_inc_scan(tot, lane);
    if (lane == 31) wsum[w] = inc;
    __syncthreads();
    if (w == 0) {
        int x = warp_inc_scan(wsum[lane], lane);
        wsum[lane] = x;
    }
    __syncthreads();
    int base = (w ? wsum[w - 1] : 0) + (inc - tot);
    int4 o;
    o.x = base;
    o.y = base + c.x;
    o.z = o.y + c.y;
    o.w = o.z + c.z;
    reinterpret_cast<int4*>(g_offset)[t] = o;
}

// ---------------------------------------------------------------------------
// Pass B: expand persisted masks (diagonal pre-cleared). One warp per row.
__global__ void fill_kernel(float* __restrict__ out, int n, int mp, int nw) {
    int row = (blockIdx.x * blockDim.x + threadIdx.x) >> 5;
    int lane = threadIdx.x & 31;
    if (row >= n) return;
    float4 pi = g_pos4[row];
    const unsigned* mrow = g_mask + (size_t)row * nw;
    int base = g_offset[row];
    float fi = (float)row;
    for (int w0 = 0; w0 < nw; w0 += 32) {
        unsigned m = mrow[w0 + lane];
        int pc = __popc(m);
        int inc = warp_inc_scan(pc, lane);
        int tot = __shfl_sync(FULLMASK, inc, 31);
        int slot = base + inc - pc;
        while (m) {
            int b = __ffs(m) - 1;
            m &= m - 1;
            int j = (w0 + lane) * 32 + b;
            float4 pj = g_pos4[j];
            float dx = __fadd_rn(pi.x, -pj.x);
            float dy = __fadd_rn(pi.y, -pj.y);
            float dz = __fadd_rn(pi.z, -pj.z);
            float d2 = __fadd_rn(__fadd_rn(__fmul_rn(dx, dx), __fmul_rn(dy, dy)),
                                 __fmul_rn(dz, dz));
            if (slot < mp) {
                out[slot]          = fi;
                out[mp + slot]     = (float)j;
                out[2 * mp + slot] = __fsqrt_rn(d2);
                float* v = out + 3 * mp + 3 * slot;
                v[0] = dx; v[1] = dy; v[2] = dz;
            }
            slot++;
        }
        base += tot;
    }
}

// ---------------------------------------------------------------------------
extern "C" void kernel_launch(void* const* d_in, const int* in_sizes, int n_in,
                              void* d_out, int out_size) {
    const float* pos   = (const float*)d_in[0];
    const int*   batch = (const int*)d_in[1];
    float* out = (float*)d_out;

    int n = in_sizes[1];
    if (n > N_MAX) n = N_MAX;
    int n_pad = (n + 31) & ~31;
    int nw = n_pad / 32;
    int mp = out_size / 6;

    pack_kernel<<<(n_pad + 255) / 256, 256>>>(pos, batch, n, n_pad);

    long long vec4 = (6LL * mp + 3) / 4;
    init_kernel<<<(int)((vec4 + 255) / 256), 256>>>(out, mp);

    dim3 mgrid((nw + 7) / 8, nw);
    mask_block_kernel<<<mgrid, 256>>>(nw);

    count_kernel<<<(n_pad * 32 + 255) / 256, 256>>>(n_pad, nw);
    scan_kernel<<<1, 1024>>>();
    fill_kernel<<<(n * 32 + 255) / 256, 256>>>(out, n, mp, nw);
}

// round 6
// speedup vs baseline: 2.1310x; 1.0073x over previous
#include <cuda_runtime.h>
#include <cstdint>

#define N_MAX 4096
#define W_MAX 128              // words per row (N_MAX/32)
#define FULLMASK 0xFFFFFFFFu

// Static scratch (allocations forbidden).
__device__ float4   g_pos4[N_MAX];
__device__ int      g_count[N_MAX];
__device__ int      g_offset[N_MAX];
__device__ unsigned g_mask[N_MAX * W_MAX];   // 2 MB ballot bitmap, row-major words

// ---------------------------------------------------------------------------
// Pack pos (N,3)+batch into float4; pad [n, n_pad) with per-row-distinct
// sentinel batch. Also zeroes g_count for ALL rows (graph-replay safe).
__global__ void pack_kernel(const float* __restrict__ pos,
                            const int* __restrict__ batch, int n, int n_pad) {
    int i = blockIdx.x * blockDim.x + threadIdx.x;
    if (i < N_MAX) g_count[i] = 0;
    if (i < n) {
        float4 p;
        p.x = pos[3 * i + 0];
        p.y = pos[3 * i + 1];
        p.z = pos[3 * i + 2];
        p.w = __int_as_float(batch[i]);
        g_pos4[i] = p;
    } else if (i < n_pad) {
        g_pos4[i] = make_float4(1e9f, 1e9f, 1e9f, __int_as_float(-2 - i));
    }
}

// Full output init: edge_index = -1, weight/vec = 0.
__global__ void init_kernel(float* __restrict__ out, int mp) {
    long long idx = (long long)(blockIdx.x * (long long)blockDim.x + threadIdx.x) * 4;
    if (idx < 6LL * mp) {
        float v = (idx < 2LL * mp) ? -1.0f : 0.0f;
        *reinterpret_cast<float4*>(out + idx) = make_float4(v, v, v, v);
    }
}

// ---------------------------------------------------------------------------
// Pass A: symmetric 32x32 tile evaluation + fused row counting.
// One warp per tile (I,J), J>=I. Lane l owns row i=I*32+l. Step k evaluates
// column j=J*32+k. Local word = row block; ballot = transposed block.
// Row counts accumulate via predicated atomics (most words are zero).
__global__ void mask_block_kernel(int nw) {
    int I = blockIdx.y;
    int wslot = threadIdx.x >> 5;
    int J = blockIdx.x * 8 + wslot;
    int lane = threadIdx.x & 31;
    if (J >= nw || J < I) return;

    __shared__ float4 sh[8][32];
    float4 pi = g_pos4[I * 32 + lane];
    sh[wslot][lane] = g_pos4[J * 32 + lane];
    __syncwarp();
    int ib = __float_as_int(pi.w);

    unsigned myword = 0;
    if (I == J) {
#pragma unroll 8
        for (int k = 0; k < 32; k++) {
            float4 q = sh[wslot][k];
            float dx = __fadd_rn(pi.x, -q.x);
            float dy = __fadd_rn(pi.y, -q.y);
            float dz = __fadd_rn(pi.z, -q.z);
            float d2 = __fadd_rn(__fadd_rn(__fmul_rn(dx, dx), __fmul_rn(dy, dy)),
                                 __fmul_rn(dz, dz));
            bool p = (ib == __float_as_int(q.w)) & (d2 < 25.0f) & (k != lane);
            if (p) p = (__fsqrt_rn(d2) < 5.0f);
            myword |= ((unsigned)p) << k;
        }
        g_mask[(size_t)(I * 32 + lane) * nw + J] = myword;
        int pc = __popc(myword);
        if (pc) atomicAdd(&g_count[I * 32 + lane], pc);
    } else {
        unsigned tword = 0;
#pragma unroll 8
        for (int k = 0; k < 32; k++) {
            float4 q = sh[wslot][k];
            float dx = __fadd_rn(pi.x, -q.x);
            float dy = __fadd_rn(pi.y, -q.y);
            float dz = __fadd_rn(pi.z, -q.z);
            float d2 = __fadd_rn(__fadd_rn(__fmul_rn(dx, dx), __fmul_rn(dy, dy)),
                                 __fmul_rn(dz, dz));
            bool p = (ib == __float_as_int(q.w)) & (d2 < 25.0f);
            if (p) p = (__fsqrt_rn(d2) < 5.0f);
            unsigned bal = __ballot_sync(FULLMASK, p);   // bit m = pred(I*32+m, J*32+k)
            myword |= ((unsigned)p) << k;
            if (lane == k) tword = bal;                  // symmetric: row J*32+k, word I
        }
        g_mask[(size_t)(I * 32 + lane) * nw + J] = myword;
        g_mask[(size_t)(J * 32 + lane) * nw + I] = tword;
        int pc0 = __popc(myword);
        int pc1 = __popc(tword);
        if (pc0) atomicAdd(&g_count[I * 32 + lane], pc0);
        if (pc1) atomicAdd(&g_count[J * 32 + lane], pc1);
    }
}

// ---------------------------------------------------------------------------
// Exclusive scan of 4096 counts (shfl, 2 barriers).
__device__ __forceinline__ int warp_inc_scan(int v, int lane) {
#pragma unroll
    for (int off = 1; off < 32; off <<= 1) {
        int u = __shfl_up_sync(FULLMASK, v, off);
        if (lane >= off) v += u;
    }
    return v;
}

__global__ void scan_kernel() {
    __shared__ int wsum[32];
    int t = threadIdx.x;            // 1024 threads x 4 counts = 4096
    int lane = t & 31, w = t >> 5;
    int4 c = reinterpret_cast<int4*>(g_count)[t];
    int tot = c.x + c.y + c.z + c.w;
    int inc = warp_inc_scan(tot, lane);
    if (lane == 31) wsum[w] = inc;
    __syncthreads();
    if (w == 0) {
        int x = warp_inc_scan(wsum[lane], lane);
        wsum[lane] = x;
    }
    __syncthreads();
    int base = (w ? wsum[w - 1] : 0) + (inc - tot);
    int4 o;
    o.x = base;
    o.y = base + c.x;
    o.z = o.y + c.y;
    o.w = o.z + c.z;
    reinterpret_cast<int4*>(g_offset)[t] = o;
}

// ---------------------------------------------------------------------------
// Pass B: expand persisted masks (diagonal pre-cleared). One warp per row.
__global__ void fill_kernel(float* __restrict__ out, int n, int mp, int nw) {
    int row = (blockIdx.x * blockDim.x + threadIdx.x) >> 5;
    int lane = threadIdx.x & 31;
    if (row >= n) return;
    float4 pi = g_pos4[row];
    const unsigned* mrow = g_mask + (size_t)row * nw;
    int base = g_offset[row];
    float fi = (float)row;
    for (int w0 = 0; w0 < nw; w0 += 32) {
        unsigned m = mrow[w0 + lane];
        int pc = __popc(m);
        int inc = warp_inc_scan(pc, lane);
        int tot = __shfl_sync(FULLMASK, inc, 31);
        int slot = base + inc - pc;
        while (m) {
            int b = __ffs(m) - 1;
            m &= m - 1;
            int j = (w0 + lane) * 32 + b;
            float4 pj = g_pos4[j];
            float dx = __fadd_rn(pi.x, -pj.x);
            float dy = __fadd_rn(pi.y, -pj.y);
            float dz = __fadd_rn(pi.z, -pj.z);
            float d2 = __fadd_rn(__fadd_rn(__fmul_rn(dx, dx), __fmul_rn(dy, dy)),
                                 __fmul_rn(dz, dz));
            if (slot < mp) {
                out[slot]          = fi;
                out[mp + slot]     = (float)j;
                out[2 * mp + slot] = __fsqrt_rn(d2);
                float* v = out + 3 * mp + 3 * slot;
                v[0] = dx; v[1] = dy; v[2] = dz;
            }
            slot++;
        }
        base += tot;
    }
}

// ---------------------------------------------------------------------------
extern "C" void kernel_launch(void* const* d_in, const int* in_sizes, int n_in,
                              void* d_out, int out_size) {
    const float* pos   = (const float*)d_in[0];
    const int*   batch = (const int*)d_in[1];
    float* out = (float*)d_out;

    int n = in_sizes[1];
    if (n > N_MAX) n = N_MAX;
    int n_pad = (n + 31) & ~31;
    int nw = n_pad / 32;
    int mp = out_size / 6;

    pack_kernel<<<(N_MAX + 255) / 256, 256>>>(pos, batch, n, n_pad);

    long long vec4 = (6LL * mp + 3) / 4;
    init_kernel<<<(int)((vec4 + 255) / 256), 256>>>(out, mp);

    dim3 mgrid((nw + 7) / 8, nw);
    mask_block_kernel<<<mgrid, 256>>>(nw);

    scan_kernel<<<1, 1024>>>();
    fill_kernel<<<(n * 32 + 255) / 256, 256>>>(out, n, mp, nw);
}